// round 1
// baseline (speedup 1.0000x reference)
#include <cuda_runtime.h>
#include <math.h>

#define HID  2048
#define NEXP 64
#define BT   64      // tokens per block
#define HK   32      // H-chunk per tile
#define BTP  68      // padded token row (float4-aligned, reduces store conflicts)
#define EP   68
#define LP   65      // logits row pad
#define MAXNB 1024

// Deterministic partial-sum scratch (no atomics).
__device__ float g_ep[MAXNB * NEXP];
__device__ float g_zp[MAXNB];

__device__ __forceinline__ bool gt_pair(float va, int ia, float vb, int ib) {
    // "greater" with jax.lax.top_k tie-break: larger value, tie -> lower index.
    return (va > vb) || (va == vb && ia < ib);
}

__global__ __launch_bounds__(128) void gate_kernel(const float* __restrict__ x,
                                                   const float* __restrict__ W,
                                                   float* __restrict__ out, int N) {
    __shared__ float xs[HK][BTP];   // transposed: xs[h][token]
    __shared__ float ws[HK][EP];    // transposed: ws[h][expert]
    __shared__ float lg[BT][LP];    // logits then scores
    __shared__ float zred[4];

    const int tid  = threadIdx.x;
    const int tx   = tid & 15;      // expert group (4 experts)
    const int ty   = tid >> 4;      // token group (8 tokens)
    const int tok0 = blockIdx.x * BT;
    const int l_row = tid >> 3;     // 0..15 (row loader)
    const int l_hq  = tid & 7;      // 0..7  (float4 within 32-wide h chunk)

    float acc[8][4];
#pragma unroll
    for (int i = 0; i < 8; i++)
#pragma unroll
        for (int j = 0; j < 4; j++) acc[i][j] = 0.f;

    for (int h0 = 0; h0 < HID; h0 += HK) {
        __syncthreads();
        float4 xv[4], wv[4];
#pragma unroll
        for (int p = 0; p < 4; p++) {
            int r = l_row + p * 16;
            xv[p] = *(const float4*)(x + (size_t)(tok0 + r) * HID + h0 + l_hq * 4);
            wv[p] = *(const float4*)(W + (size_t)r * HID + h0 + l_hq * 4);
        }
#pragma unroll
        for (int p = 0; p < 4; p++) {
            int r = l_row + p * 16;
            xs[l_hq * 4 + 0][r] = xv[p].x;
            xs[l_hq * 4 + 1][r] = xv[p].y;
            xs[l_hq * 4 + 2][r] = xv[p].z;
            xs[l_hq * 4 + 3][r] = xv[p].w;
            ws[l_hq * 4 + 0][r] = wv[p].x;
            ws[l_hq * 4 + 1][r] = wv[p].y;
            ws[l_hq * 4 + 2][r] = wv[p].z;
            ws[l_hq * 4 + 3][r] = wv[p].w;
        }
        __syncthreads();
#pragma unroll
        for (int h = 0; h < HK; h++) {
            float4 xa = *(const float4*)&xs[h][ty * 8];
            float4 xb = *(const float4*)&xs[h][ty * 8 + 4];
            float4 wa = *(const float4*)&ws[h][tx * 4];
            float xr[8] = {xa.x, xa.y, xa.z, xa.w, xb.x, xb.y, xb.z, xb.w};
            float wr[4] = {wa.x, wa.y, wa.z, wa.w};
#pragma unroll
            for (int i = 0; i < 8; i++)
#pragma unroll
                for (int j = 0; j < 4; j++)
                    acc[i][j] = fmaf(xr[i], wr[j], acc[i][j]);
        }
    }
    __syncthreads();
#pragma unroll
    for (int i = 0; i < 8; i++)
#pragma unroll
        for (int j = 0; j < 4; j++)
            lg[ty * 8 + i][tx * 4 + j] = acc[i][j];
    __syncthreads();

    // ---- per-token softmax + top-2 (temperature = 1.0) ----
    const int lane = tid & 31, wrp = tid >> 5;
    float zacc = 0.f;
    for (int t = wrp * 16; t < wrp * 16 + 16; t++) {
        float l0 = lg[t][lane], l1 = lg[t][lane + 32];
        float m = fmaxf(l0, l1);
#pragma unroll
        for (int o = 16; o; o >>= 1) m = fmaxf(m, __shfl_xor_sync(0xffffffffu, m, o));
        float p0 = expf(l0 - m), p1 = expf(l1 - m);
        float s = p0 + p1;
#pragma unroll
        for (int o = 16; o; o >>= 1) s += __shfl_xor_sync(0xffffffffu, s, o);
        float inv = 1.f / s;
        float q0 = p0 * inv, q1 = p1 * inv;
        lg[t][lane] = q0;            // scores back into smem (for expert-load sums)
        lg[t][lane + 32] = q1;

        float v0, v1; int i0, i1;
        if (q0 >= q1) { v0 = q0; i0 = lane;      v1 = q1; i1 = lane + 32; }
        else          { v0 = q1; i0 = lane + 32; v1 = q0; i1 = lane; }
#pragma unroll
        for (int o = 16; o; o >>= 1) {
            float b0 = __shfl_xor_sync(0xffffffffu, v0, o);
            int   j0 = __shfl_xor_sync(0xffffffffu, i0, o);
            float b1 = __shfl_xor_sync(0xffffffffu, v1, o);
            int   j1 = __shfl_xor_sync(0xffffffffu, i1, o);
            if (gt_pair(b0, j0, v0, i0)) {
                if (gt_pair(v0, i0, b1, j1)) { v1 = v0; i1 = i0; }
                else                         { v1 = b1; i1 = j1; }
                v0 = b0; i0 = j0;
            } else if (gt_pair(b0, j0, v1, i1)) { v1 = b0; i1 = j0; }
        }
        if (lane == 0) {
            int g = tok0 + t;
            float ed = expf(v1 - v0);
            float r0 = 1.f / (1.f + ed);
            out[2 * g]     = r0;          // softmax over the two top scores
            out[2 * g + 1] = ed * r0;
            out[2 * N + 2 * g]     = (float)i0;
            out[2 * N + 2 * g + 1] = (float)i1;
            float ls = m + logf(s);       // logsumexp(logits)
            zacc += ls * ls;
        }
    }
    if (lane == 0) zred[wrp] = zacc;
    __syncthreads();

    // expert-load partials (column sums of scores), conflict-free (LP=65)
    if (tid < NEXP) {
        float cs = 0.f;
#pragma unroll 8
        for (int t = 0; t < BT; t++) cs += lg[t][tid];
        g_ep[blockIdx.x * NEXP + tid] = cs;
    }
    if (tid == 0) g_zp[blockIdx.x] = zred[0] + zred[1] + zred[2] + zred[3];
}

__global__ void reduce_kernel(float* __restrict__ out, int NB, int N) {
    __shared__ float red[256];
    int t = threadIdx.x;
    float v = 0.f;
    if (t < NEXP) {
        float s = 0.f;
        for (int b = 0; b < NB; b++) s += g_ep[b * NEXP + t];
        float load = s / (float)N;
        float d = load - 1.0f / (float)NEXP;
        v = 0.01f * d * d;              // LOAD_BALANCE_ALPHA
    }
    float z = 0.f;
    for (int b = t; b < NB; b += 256) z += g_zp[b];
    red[t] = v + 1e-4f * z / (float)N;  // Z_LOSS_ALPHA * mean(lse^2)
    __syncthreads();
    for (int s2 = 128; s2; s2 >>= 1) {
        if (t < s2) red[t] += red[t + s2];
        __syncthreads();
    }
    if (t == 0) out[4 * N] = red[0];
}

extern "C" void kernel_launch(void* const* d_in, const int* in_sizes, int n_in,
                              void* d_out, int out_size) {
    const float* x = (const float*)d_in[0];
    const float* W = (const float*)d_in[1];
    float* out = (float*)d_out;
    int N  = in_sizes[0] / HID;   // 16384 tokens
    int NB = N / BT;              // 256 blocks
    gate_kernel<<<NB, 128>>>(x, W, out, N);
    reduce_kernel<<<1, 256>>>(out, NB, N);
}